// round 4
// baseline (speedup 1.0000x reference)
#include <cuda_runtime.h>
#include <cstdint>

#define FULLMASK 0xffffffffu

// Scratch (device globals — no allocation allowed)
__device__ float g_feat[32 * 2048];        // [b][2048]  (pos | neg features)
__device__ float g_part[64 * 32 * 1024];   // [kg][b][c] split-K partials

// Monotone float -> uint key (ascending). key(-f) == ~key(f).
__device__ __forceinline__ unsigned key_encode(float f) {
    unsigned u = __float_as_uint(f);
    return (u & 0x80000000u) ? ~u : (u | 0x80000000u);
}
__device__ __forceinline__ float key_decode(unsigned k) {
    unsigned u = (k & 0x80000000u) ? (k & 0x7fffffffu) : ~k;
    return __uint_as_float(u);
}

// ---------------------------------------------------------------------------
// Kernel 1: per batch row b — row norms + exact top16(h) / top16(-h) sums via
// REDUX.MAX tournament (no atomics, no histograms).
// 512 threads: warps 0-7 select on keys (pos), warps 8-15 on ~keys (neg),
// each warp owns 256 histo elements (8/lane). Warp 0 / warp 8 merge.
// grid 32, block 512.
// ---------------------------------------------------------------------------
__global__ void __launch_bounds__(512) k1_stats_feat(
        const float* __restrict__ f_rad, const float* __restrict__ f_histo) {
    const int b    = blockIdx.x;
    const int tid  = threadIdx.x;
    const int lane = tid & 31;
    const int wid  = tid >> 5;     // 0..15
    const int grp  = wid >> 3;     // 0 = pos keys, 1 = neg keys
    const int w8   = wid & 7;      // warp within group
    const int t8   = tid & 255;    // element owner index within group
    const float* __restrict__ hrow = f_histo + b * 2048;
    const float* __restrict__ rrow = f_rad   + b * 1024;

    __shared__ unsigned cand[2][128];   // per-group 8 warps x 16 candidate keys
    __shared__ float    s_redh[8];      // ssh partials (group 0 warps)
    __shared__ float    s_redr[16];     // ssr partials (all warps)
    __shared__ float    s_out[2];       // top16 sums (pos, neg-of)
    __shared__ float    s_bcast[3];

    // --- load histo slice (8/lane), encode keys; sums of squares ---
    unsigned k[8];
    float ssh = 0.f, ssr = 0.f;
    #pragma unroll
    for (int u = 0; u < 8; ++u) {
        float v = hrow[u * 256 + t8];
        if (grp == 0) ssh += v * v;
        unsigned e = key_encode(v);
        k[u] = grp ? ~e : e;
    }
    #pragma unroll
    for (int u = 0; u < 2; ++u) {
        float v = rrow[u * 512 + tid];
        ssr += v * v;
    }

    // --- warp pop-16: repeatedly extract the max key of the warp's 256 ---
    unsigned lm = k[0];
    #pragma unroll
    for (int j = 1; j < 8; ++j) lm = max(lm, k[j]);
    for (int r = 0; r < 16; ++r) {
        unsigned m    = __reduce_max_sync(FULLMASK, lm);
        unsigned ball = __ballot_sync(FULLMASK, lm == m);
        if (lane == __ffs(ball) - 1) {
            bool done = false;
            #pragma unroll
            for (int j = 0; j < 8; ++j)
                if (!done && k[j] == m) { k[j] = 0u; done = true; }
            lm = k[0];
            #pragma unroll
            for (int j = 1; j < 8; ++j) lm = max(lm, k[j]);
        }
        if (lane == 0) cand[grp][w8 * 16 + r] = m;
    }

    // --- norm partial reductions ---
    #pragma unroll
    for (int o = 16; o; o >>= 1) {
        ssh += __shfl_xor_sync(FULLMASK, ssh, o);
        ssr += __shfl_xor_sync(FULLMASK, ssr, o);
    }
    if (lane == 0) {
        if (grp == 0) s_redh[w8] = ssh;
        s_redr[wid] = ssr;
    }
    __syncthreads();

    // --- merge: warp 0 merges pos candidates, warp 8 merges neg ---
    if (w8 == 0) {
        unsigned c[4];
        #pragma unroll
        for (int j = 0; j < 4; ++j) c[j] = cand[grp][lane * 4 + j];
        unsigned mlm = c[0];
        #pragma unroll
        for (int j = 1; j < 4; ++j) mlm = max(mlm, c[j]);
        float sum = 0.f;
        for (int r = 0; r < 16; ++r) {
            unsigned m    = __reduce_max_sync(FULLMASK, mlm);
            unsigned ball = __ballot_sync(FULLMASK, mlm == m);
            sum += key_decode(m);
            if (lane == __ffs(ball) - 1) {
                bool done = false;
                #pragma unroll
                for (int j = 0; j < 4; ++j)
                    if (!done && c[j] == m) { c[j] = 0u; done = true; }
                mlm = c[0];
                #pragma unroll
                for (int j = 1; j < 4; ++j) mlm = max(mlm, c[j]);
            }
        }
        if (lane == 0) s_out[grp] = sum;
    }
    __syncthreads();

    if (tid == 0) {
        float a0 = 0.f, a1 = 0.f;
        #pragma unroll
        for (int w = 0; w < 8; ++w)  a0 += s_redh[w];
        #pragma unroll
        for (int w = 0; w < 16; ++w) a1 += s_redr[w];
        float nh  = fmaxf(sqrtf(a0), 1e-12f);
        float nr  = fmaxf(sqrtf(a1), 1e-12f);
        s_bcast[0] = 1.f / nr;
        s_bcast[1] = s_out[0] / (16.f * nh);    // T  = mean(top16(h_norm))
        s_bcast[2] = -s_out[1] / (16.f * nh);   // Bt = mean(bottom16(h_norm))
    }
    __syncthreads();

    const float inv_nr = s_bcast[0];
    const float T      = s_bcast[1];
    const float Bt     = s_bcast[2];
    float* __restrict__ fout = g_feat + b * 2048;
    #pragma unroll
    for (int u = 0; u < 2; ++u) {
        int   i  = u * 512 + tid;
        float rv = rrow[i] * inv_nr;
        float pm, nm;
        if (rv >= 0.f) { pm = rv * T;  nm = -rv * Bt; }
        else           { pm = rv * Bt; nm = -rv * T;  }
        fout[i]        = pm;
        fout[1024 + i] = nm;
    }
}

// ---------------------------------------------------------------------------
// Kernel 2: split-K fp32 GEMM partials. 128 threads (4 warps, 1 per SMSP),
// block tile 32b x 256c x 32k; warp w covers c in [w*64, w*64+64);
// thread tile 8b x 8c interleaved (b = bl+4i, c = w*64 + cl + 8j).
// Smem rows padded to 36 floats -> float4 bank-group (row+q) mod 8:
// conflict-free / broadcast vector loads. grid (4 cblk, 64 kg).
// ---------------------------------------------------------------------------
__global__ void __launch_bounds__(128) k2_gemm(const float* __restrict__ W) {
    __shared__ float Ws[256 * 36];
    __shared__ float Fs[32 * 36];
    const int tid = threadIdx.x;
    const int lane = tid & 31;
    const int wid  = tid >> 5;
    const int c0  = blockIdx.x * 256;
    const int kg  = blockIdx.y;
    const int k0  = kg * 32;

    // Load W tile 256c x 32k (2048 float4) and feat tile 32b x 32k (256 float4).
    #pragma unroll
    for (int it = 0; it < 16; ++it) {
        int idx = it * 128 + tid;       // float4 id
        int r   = idx >> 3;             // 0..255
        int q   = idx & 7;              // 0..7
        float4 v = *(const float4*)&W[(c0 + r) * 2048 + k0 + q * 4];
        *(float4*)&Ws[r * 36 + q * 4] = v;
    }
    #pragma unroll
    for (int it = 0; it < 2; ++it) {
        int idx = it * 128 + tid;
        int r   = idx >> 3;             // 0..31
        int q   = idx & 7;
        float4 v = *(const float4*)&g_feat[r * 2048 + k0 + q * 4];
        *(float4*)&Fs[r * 36 + q * 4] = v;
    }
    __syncthreads();

    const int bl = lane >> 3;   // 0..3 : b rows  bl, bl+4, ..., bl+28
    const int cl = lane & 7;    // 0..7 : c cols  w*64 + cl + 8j
    const float* __restrict__ wbase = &Ws[(wid * 64 + cl) * 36];

    float acc[8][8];
    #pragma unroll
    for (int i = 0; i < 8; ++i)
        #pragma unroll
        for (int j = 0; j < 8; ++j) acc[i][j] = 0.f;

    #pragma unroll
    for (int kq = 0; kq < 8; ++kq) {
        float4 f[8], w[8];
        #pragma unroll
        for (int i = 0; i < 8; ++i)
            f[i] = *(const float4*)&Fs[(bl + 4 * i) * 36 + kq * 4];
        #pragma unroll
        for (int j = 0; j < 8; ++j)
            w[j] = *(const float4*)&wbase[(8 * j) * 36 + kq * 4];
        #pragma unroll
        for (int i = 0; i < 8; ++i)
            #pragma unroll
            for (int j = 0; j < 8; ++j) {
                acc[i][j] = fmaf(f[i].x, w[j].x, acc[i][j]);
                acc[i][j] = fmaf(f[i].y, w[j].y, acc[i][j]);
                acc[i][j] = fmaf(f[i].z, w[j].z, acc[i][j]);
                acc[i][j] = fmaf(f[i].w, w[j].w, acc[i][j]);
            }
    }

    float* __restrict__ outp = g_part + kg * (32 * 1024) + c0 + wid * 64;
    #pragma unroll
    for (int i = 0; i < 8; ++i) {
        #pragma unroll
        for (int j = 0; j < 8; ++j)
            outp[(bl + 4 * i) * 1024 + cl + 8 * j] = acc[i][j];
    }
}

// ---------------------------------------------------------------------------
// Kernel 3: reduce 64 split-K partials + bias + token * flag. grid 64, blk 128.
// ---------------------------------------------------------------------------
__global__ void __launch_bounds__(128) k3_reduce(
        const float* __restrict__ bias, const float* __restrict__ token,
        const unsigned char* __restrict__ rad_mask,
        const unsigned char* __restrict__ histo_mask,
        float* __restrict__ out) {
    int gid = blockIdx.x * 128 + threadIdx.x;   // float4 id 0..8191
    int b   = gid >> 8;
    int c4  = gid & 255;

    float4 acc = *(const float4*)&bias[c4 * 4];
    #pragma unroll
    for (int g = 0; g < 64; ++g) {
        float4 p = *(const float4*)&g_part[g * 32768 + b * 1024 + c4 * 4];
        acc.x += p.x; acc.y += p.y; acc.z += p.z; acc.w += p.w;
    }
    float flag = (rad_mask[b] != 0 && histo_mask[b] != 0) ? 0.f : 1.f;
    float4 tk  = *(const float4*)&token[c4 * 4];
    acc.x += tk.x * flag; acc.y += tk.y * flag;
    acc.z += tk.z * flag; acc.w += tk.w * flag;
    *(float4*)&out[b * 1024 + c4 * 4] = acc;
}

// ---------------------------------------------------------------------------
extern "C" void kernel_launch(void* const* d_in, const int* in_sizes, int n_in,
                              void* d_out, int out_size) {
    const float*         f_rad      = (const float*)d_in[0];
    const float*         f_histo    = (const float*)d_in[1];
    const unsigned char* rad_mask   = (const unsigned char*)d_in[2];
    const unsigned char* histo_mask = (const unsigned char*)d_in[3];
    const float*         W          = (const float*)d_in[4];
    const float*         bias       = (const float*)d_in[5];
    const float*         token      = (const float*)d_in[6];
    float*               out        = (float*)d_out;

    k1_stats_feat<<<32, 512>>>(f_rad, f_histo);
    k2_gemm<<<dim3(4, 64), 128>>>(W);
    k3_reduce<<<64, 128>>>(bias, token, rad_mask, histo_mask, out);
}

// round 5
// speedup vs baseline: 1.1099x; 1.1099x over previous
#include <cuda_runtime.h>
#include <cstdint>

#define FULLMASK 0xffffffffu

// Scratch (device globals — no allocation allowed)
// g_stats[b] = {ssh, ssr, sum_top16(h), sum_top16(-h)}  (raw, un-normalized)
__device__ float g_stats[32][4];
__device__ float g_part[32 * 32 * 1024];   // [kg][b][c] split-K partials

// Monotone float -> uint key (ascending).
__device__ __forceinline__ unsigned key_encode(float f) {
    unsigned u = __float_as_uint(f);
    return (u & 0x80000000u) ? ~u : (u | 0x80000000u);
}
__device__ __forceinline__ float key_decode(unsigned k) {
    unsigned u = (k & 0x80000000u) ? (k & 0x7fffffffu) : ~k;
    return __uint_as_float(u);
}

// ---------------------------------------------------------------------------
// Kernel 1: stats only. grid 64 = (row b, sign s). block 256.
//   s=0: ssh = ||f_histo[b]||^2 and sum of top16(f_histo[b])
//   s=1: ssr = ||f_rad[b]||^2  and sum of top16(-f_histo[b])
// Selection: 4-pass MSB-first 8-bit radix over monotone keys, with
// warp-private histograms (8 warps x 256 bins) -> bounded ATOMS cost.
// ---------------------------------------------------------------------------
__global__ void __launch_bounds__(256) k1_stats(
        const float* __restrict__ f_rad, const float* __restrict__ f_histo) {
    const int b    = blockIdx.x >> 1;
    const int s    = blockIdx.x & 1;
    const int tid  = threadIdx.x;
    const int lane = tid & 31;
    const int wid  = tid >> 5;
    const float* __restrict__ hrow = f_histo + b * 2048;
    const float* __restrict__ rrow = f_rad   + b * 1024;

    __shared__ unsigned hist[8][256];
    __shared__ unsigned s_thr, s_rem;
    __shared__ unsigned s_wtot[8];
    __shared__ float    s_red[2][8];

    // --- load 2048 histo elements (8/thread), encode keys; sum-of-squares ---
    float hv[8];
    float ssq = 0.f;
    #pragma unroll
    for (int u = 0; u < 8; ++u) {
        float v = hrow[u * 256 + tid];
        hv[u] = v;
        if (s == 0) ssq += v * v;
    }
    if (s == 1) {
        #pragma unroll
        for (int u = 0; u < 4; ++u) {
            float v = rrow[u * 256 + tid];
            ssq += v * v;
        }
    }
    unsigned keys[8];
    #pragma unroll
    for (int u = 0; u < 8; ++u) {
        unsigned e = key_encode(hv[u]);
        keys[u] = s ? ~e : e;
    }

    if (tid == 0) { s_thr = 0u; s_rem = 16u; }
    __syncthreads();

    // --- 4 radix passes, MSB byte first ---
    #pragma unroll
    for (int p = 3; p >= 0; --p) {
        const int shift = 8 * p;
        const unsigned mhi = (p == 3) ? 0u : (0xFFFFFFFFu << (shift + 8));
        const unsigned pfx = s_thr;
        const unsigned rem = s_rem;

        // zero this warp's private histogram
        #pragma unroll
        for (int j = 0; j < 8; ++j) hist[wid][lane + 32 * j] = 0u;
        __syncwarp();

        #pragma unroll
        for (int u = 0; u < 8; ++u) {
            unsigned k = keys[u];
            if ((k & mhi) == pfx)
                atomicAdd(&hist[wid][(k >> shift) & 255u], 1u);
        }
        __syncthreads();

        // merge 8 private histograms; suffix-scan over 256 bins (bin = tid)
        unsigned c = 0u;
        #pragma unroll
        for (int w = 0; w < 8; ++w) c += hist[w][tid];
        unsigned inc = c;
        #pragma unroll
        for (int o = 1; o < 32; o <<= 1) {
            unsigned v = __shfl_down_sync(FULLMASK, inc, o);
            if (lane + o < 32) inc += v;
        }
        if (lane == 0) s_wtot[wid] = inc;
        __syncthreads();
        unsigned hi = 0u;
        #pragma unroll
        for (int w = 0; w < 8; ++w)
            if (w > wid) hi += s_wtot[w];
        unsigned cum = (inc - c) + hi;   // count of keys in bins strictly above
        if (cum < rem && cum + c >= rem) {
            atomicOr(&s_thr, (unsigned)tid << shift);
            s_rem = rem - cum;
        }
        __syncthreads();
    }

    const unsigned T0 = s_thr, rem0 = s_rem;

    // sum of values whose key is strictly greater than threshold
    float sum = 0.f;
    #pragma unroll
    for (int u = 0; u < 8; ++u) {
        float val = s ? -hv[u] : hv[u];
        if (keys[u] > T0) sum += val;
    }

    // block-reduce {ssq, sum}
    #pragma unroll
    for (int o = 16; o; o >>= 1) {
        ssq += __shfl_xor_sync(FULLMASK, ssq, o);
        sum += __shfl_xor_sync(FULLMASK, sum, o);
    }
    if (lane == 0) { s_red[0][wid] = ssq; s_red[1][wid] = sum; }
    __syncthreads();
    if (tid == 0) {
        float a0 = 0.f, a1 = 0.f;
        #pragma unroll
        for (int w = 0; w < 8; ++w) { a0 += s_red[0][w]; a1 += s_red[1][w]; }
        // boundary value: decode threshold key in the ORIGINAL value space
        float tv = s ? -key_decode(~T0) : key_decode(T0);
        a1 += (float)rem0 * tv;
        if (s == 0) { g_stats[b][0] = a0; g_stats[b][2] = a1; }
        else        { g_stats[b][1] = a0; g_stats[b][3] = a1; }
    }
}

// ---------------------------------------------------------------------------
// Kernel 2: split-K fp32 GEMM with feat computed inline from f_rad + stats.
// Block tile 32b x 64c x 64k, 32 threads, thread tile 8b x 8c interleaved.
// Smem rows padded to 68 floats (conflict-free float4 access).
// grid (16 cblk, 32 kg): kg<16 -> pos half of feat, kg>=16 -> neg half.
// ---------------------------------------------------------------------------
__global__ void __launch_bounds__(32) k2_gemm(const float* __restrict__ W,
                                              const float* __restrict__ f_rad) {
    __shared__ float Ws[64 * 68];
    __shared__ float Fs[32 * 68];
    __shared__ float sm_ca[32], sm_cb[32];
    const int tid = threadIdx.x;
    const int c0  = blockIdx.x * 64;
    const int kg  = blockIdx.y;
    const int k0  = kg * 64;           // global feat column base
    const bool pos_half = (kg < 16);
    const int i0  = (kg & 15) * 64;    // f_rad column base for this k-slice

    // Per-row coefficients: feat = fr * (fr>=0 ? ca : cb)
    {
        float4 st = *(const float4*)&g_stats[tid][0];   // ssh, ssr, top, bng
        float nh = fmaxf(sqrtf(st.x), 1e-12f);
        float nr = fmaxf(sqrtf(st.y), 1e-12f);
        float inv_nr = 1.f / nr;
        float T  = st.z / (16.f * nh);    // mean(top16(h_norm))
        float Bt = -st.w / (16.f * nh);   // mean(bottom16(h_norm))
        if (pos_half) { sm_ca[tid] = inv_nr * T;   sm_cb[tid] = inv_nr * Bt; }
        else          { sm_ca[tid] = -inv_nr * Bt; sm_cb[tid] = -inv_nr * T; }
    }
    __syncwarp();

    // Load W tile 64c x 64k (1024 float4).
    #pragma unroll
    for (int it = 0; it < 32; ++it) {
        int idx = it * 32 + tid;
        int r   = idx >> 4;               // 0..63
        int q   = idx & 15;               // 0..15
        float4 v = *(const float4*)&W[(c0 + r) * 2048 + k0 + q * 4];
        *(float4*)&Ws[r * 68 + q * 4] = v;
    }
    // Build feat tile 32b x 64k inline from f_rad (512 float4).
    #pragma unroll
    for (int it = 0; it < 16; ++it) {
        int idx = it * 32 + tid;
        int r   = idx >> 4;               // 0..31
        int q   = idx & 15;
        float4 f = *(const float4*)&f_rad[r * 1024 + i0 + q * 4];
        float ca = sm_ca[r], cb = sm_cb[r];
        float4 v;
        v.x = f.x * (f.x >= 0.f ? ca : cb);
        v.y = f.y * (f.y >= 0.f ? ca : cb);
        v.z = f.z * (f.z >= 0.f ? ca : cb);
        v.w = f.w * (f.w >= 0.f ? ca : cb);
        *(float4*)&Fs[r * 68 + q * 4] = v;
    }
    __syncwarp();

    const int bl = tid >> 3;   // 0..3 : b rows  bl, bl+4, ..., bl+28
    const int cl = tid & 7;    // 0..7 : c cols  cl, cl+8, ..., cl+56

    float acc[8][8];
    #pragma unroll
    for (int i = 0; i < 8; ++i)
        #pragma unroll
        for (int j = 0; j < 8; ++j) acc[i][j] = 0.f;

    #pragma unroll
    for (int kq = 0; kq < 16; ++kq) {
        float4 f[8], w[8];
        #pragma unroll
        for (int i = 0; i < 8; ++i)
            f[i] = *(const float4*)&Fs[(bl + 4 * i) * 68 + kq * 4];
        #pragma unroll
        for (int j = 0; j < 8; ++j)
            w[j] = *(const float4*)&Ws[(cl + 8 * j) * 68 + kq * 4];
        #pragma unroll
        for (int i = 0; i < 8; ++i)
            #pragma unroll
            for (int j = 0; j < 8; ++j) {
                acc[i][j] = fmaf(f[i].x, w[j].x, acc[i][j]);
                acc[i][j] = fmaf(f[i].y, w[j].y, acc[i][j]);
                acc[i][j] = fmaf(f[i].z, w[j].z, acc[i][j]);
                acc[i][j] = fmaf(f[i].w, w[j].w, acc[i][j]);
            }
    }

    float* __restrict__ outp = g_part + kg * (32 * 1024) + c0;
    #pragma unroll
    for (int i = 0; i < 8; ++i) {
        #pragma unroll
        for (int j = 0; j < 8; ++j)
            outp[(bl + 4 * i) * 1024 + cl + 8 * j] = acc[i][j];
    }
}

// ---------------------------------------------------------------------------
// Kernel 3: reduce 32 split-K partials + bias + token * flag. grid 64, blk 128.
// ---------------------------------------------------------------------------
__global__ void __launch_bounds__(128) k3_reduce(
        const float* __restrict__ bias, const float* __restrict__ token,
        const unsigned char* __restrict__ rad_mask,
        const unsigned char* __restrict__ histo_mask,
        float* __restrict__ out) {
    int gid = blockIdx.x * 128 + threadIdx.x;   // float4 id 0..8191
    int b   = gid >> 8;
    int c4  = gid & 255;

    float4 acc = *(const float4*)&bias[c4 * 4];
    #pragma unroll
    for (int g = 0; g < 32; ++g) {
        float4 p = *(const float4*)&g_part[g * 32768 + b * 1024 + c4 * 4];
        acc.x += p.x; acc.y += p.y; acc.z += p.z; acc.w += p.w;
    }
    float flag = (rad_mask[b] != 0 && histo_mask[b] != 0) ? 0.f : 1.f;
    float4 tk  = *(const float4*)&token[c4 * 4];
    acc.x += tk.x * flag; acc.y += tk.y * flag;
    acc.z += tk.z * flag; acc.w += tk.w * flag;
    *(float4*)&out[b * 1024 + c4 * 4] = acc;
}

// ---------------------------------------------------------------------------
extern "C" void kernel_launch(void* const* d_in, const int* in_sizes, int n_in,
                              void* d_out, int out_size) {
    const float*         f_rad      = (const float*)d_in[0];
    const float*         f_histo    = (const float*)d_in[1];
    const unsigned char* rad_mask   = (const unsigned char*)d_in[2];
    const unsigned char* histo_mask = (const unsigned char*)d_in[3];
    const float*         W          = (const float*)d_in[4];
    const float*         bias       = (const float*)d_in[5];
    const float*         token      = (const float*)d_in[6];
    float*               out        = (float*)d_out;

    k1_stats<<<64, 256>>>(f_rad, f_histo);
    k2_gemm<<<dim3(16, 32), 32>>>(W, f_rad);
    k3_reduce<<<64, 128>>>(bias, token, rad_mask, histo_mask, out);
}